// round 11
// baseline (speedup 1.0000x reference)
#include <cuda_runtime.h>
#include <math.h>

// RoIPooling: feat [B,C,50,50] f32, rois [N,5] f32, img scalars -> out [N,C,7,7] f32.
// Bench: B=2, C=256, N=128, IMG=800.
//
// K1: R6's exact transpose (best measured): 32x32 tiles, 1264 blocks,
//     one LDG.128 + one STG.128 per thread.
// K2: block per bin (6272 x 64 thr); thread = 4 channels (float4 loads via
//     block-uniform smem offset table); DIRECT scattered stores to out
//     (no outT buffer, no third kernel).

#define C_DIM 256
#define FH 50
#define FW 50
#define NPIX (FH * FW)
#define OH 7
#define OW 7
#define QD (OH * OW)
#define MAX_B 4
#define MAX_CNT 96

__device__ __align__(16) float g_featT[MAX_B * NPIX * C_DIM];   // [b][p][c]

__device__ __forceinline__ float decode_dim(const void* p) {
    int v = *reinterpret_cast<const int*>(p);
    if (v > 0 && v < 1000000) return (float)v;   // int scalar (800 = 0x320)
    return __int_as_float(v);                     // float bits
}

__device__ __forceinline__ float4 f4max(float4 a, float4 b) {
    return make_float4(fmaxf(a.x, b.x), fmaxf(a.y, b.y),
                       fmaxf(a.z, b.z), fmaxf(a.w, b.w));
}

// ---- K1: feat [b][c][p] -> featT [b][p][c]; 32x32 tiles, float4 both sides ----
__global__ void __launch_bounds__(256)
transpose_in(const float* __restrict__ feat) {
    __shared__ float s[32][33];
    int b   = blockIdx.z;
    int tp0 = blockIdx.x * 32;       // pixel tile base
    int tc0 = blockIdx.y * 32;       // channel tile base
    int tid = threadIdx.x;           // 0..255

    {
        int cl = tid >> 3;
        int p0 = tp0 + ((tid & 7) << 2);
        if (p0 < NPIX) {             // NPIX%4==0, p0%4==0 -> p0+3 < NPIX
            float4 v = *reinterpret_cast<const float4*>(
                feat + ((size_t)(b * C_DIM + tc0 + cl)) * NPIX + p0);
            int pl = (tid & 7) << 2;
            s[cl][pl + 0] = v.x;
            s[cl][pl + 1] = v.y;
            s[cl][pl + 2] = v.z;
            s[cl][pl + 3] = v.w;
        }
    }
    __syncthreads();
    {
        int pl = tid >> 3;
        int p  = tp0 + pl;
        if (p < NPIX) {
            int c0 = (tid & 7) << 2;
            float4 v;
            v.x = s[c0 + 0][pl];
            v.y = s[c0 + 1][pl];
            v.z = s[c0 + 2][pl];
            v.w = s[c0 + 3][pl];
            *reinterpret_cast<float4*>(
                g_featT + ((size_t)b * NPIX + p) * C_DIM + tc0 + c0) = v;
        }
    }
}

// ---- K2: block per bin; 64 threads; thread = 4 channels; direct stores ----
__global__ void __launch_bounds__(64)
roipool_main(const float* __restrict__ rois,
             const void* __restrict__ img_h_p,
             const void* __restrict__ img_w_p,
             float* __restrict__ out) {
    int bin = blockIdx.x;
    int t   = threadIdx.x;           // 0..63
    int ow = bin % OW;
    int oh = (bin / OW) % OH;
    int n  = bin / QD;

    __shared__ int s_offs[MAX_CNT];  // featT element offsets, pre-multiplied by C_DIM

    // block-uniform bound math (identical in all threads; exact reference rounding)
    float img_h = decode_dim(img_h_p);
    float img_w = decode_dim(img_w_p);
    float sh = __fdiv_rn((float)FH, img_h);
    float sw = __fdiv_rn((float)FW, img_w);

    const float* r = rois + n * 5;
    int bidx = (int)r[0];
    int x1 = max((int)floorf(__fmul_rn(r[1], sw)), 0);
    int y1 = max((int)floorf(__fmul_rn(r[2], sh)), 0);
    int x2 = min((int)floorf(__fmul_rn(r[3], sw)), FW);
    int y2 = min((int)floorf(__fmul_rn(r[4], sh)), FH);

    float bh = __fdiv_rn((float)max(y2 - y1, 1), (float)OH);
    float bw = __fdiv_rn((float)max(x2 - x1, 1), (float)OW);
    float y1f = (float)y1, x1f = (float)x1;
    // mul then add, each correctly rounded (no FMA contraction) — matches jnp
    int ys = (int)floorf(__fadd_rn(y1f, __fmul_rn((float)oh,       bh)));
    int ye = (int)floorf(__fadd_rn(y1f, __fmul_rn((float)(oh + 1), bh)));
    int xs = (int)floorf(__fadd_rn(x1f, __fmul_rn((float)ow,       bw)));
    int xe = (int)floorf(__fadd_rn(x1f, __fmul_rn((float)(ow + 1), bw)));
    ys = min(max(ys, 0), FH - 1);
    ye = min(max(ye, 0), FH);
    xs = min(max(xs, 0), FW - 1);
    xe = min(max(xe, 0), FW);

    int rows = ye - ys;
    int cols = xe - xs;
    int count = (rows > 0 && cols > 0) ? rows * cols : 0;

    if (t < count) {
        int yy = ys + t / cols;
        int xx = xs + t % cols;
        s_offs[t] = (yy * FW + xx) * C_DIM;
    }
    __syncthreads();

    const float* base = g_featT + (size_t)bidx * (NPIX * C_DIM) + (t << 2);

    float4 m = make_float4(-INFINITY, -INFINITY, -INFINITY, -INFINITY);
    int i = 0;
    for (; i + 4 <= count; i += 4) {
        float4 a0 = *reinterpret_cast<const float4*>(base + s_offs[i + 0]);
        float4 a1 = *reinterpret_cast<const float4*>(base + s_offs[i + 1]);
        float4 a2 = *reinterpret_cast<const float4*>(base + s_offs[i + 2]);
        float4 a3 = *reinterpret_cast<const float4*>(base + s_offs[i + 3]);
        m = f4max(m, f4max(f4max(a0, a1), f4max(a2, a3)));
    }
    for (; i < count; ++i) {
        m = f4max(m, *reinterpret_cast<const float4*>(base + s_offs[i]));
    }
    if (count == 0) m = make_float4(0.f, 0.f, 0.f, 0.f);

    // direct scattered stores: out[n][c][q], c = 4t..4t+3, q = oh*OW+ow
    int q = oh * OW + ow;
    float* op = out + ((size_t)n * C_DIM + (t << 2)) * QD + q;
    op[0 * QD] = m.x;
    op[1 * QD] = m.y;
    op[2 * QD] = m.z;
    op[3 * QD] = m.w;
}

extern "C" void kernel_launch(void* const* d_in, const int* in_sizes, int n_in,
                              void* d_out, int out_size) {
    const float* feat = (const float*)d_in[0];
    const float* rois = (const float*)d_in[1];
    const void*  imh  = d_in[2];
    const void*  imw  = d_in[3];
    float* out = (float*)d_out;

    int B = in_sizes[0] / (C_DIM * NPIX);
    int nrois = in_sizes[1] / 5;
    int nbins = nrois * QD;

    dim3 tg((NPIX + 31) / 32, C_DIM / 32, B);
    transpose_in<<<tg, 256>>>(feat);

    roipool_main<<<nbins, 64>>>(rois, imh, imw, out);
}